// round 4
// baseline (speedup 1.0000x reference)
#include <cuda_runtime.h>
#include <cfloat>
#include <cstdint>

#define DT     0.01f
#define SIGMA  0.5f
#define NSTEP  50
#define BATCH  262144
#define NTAB   101     // 51 Y-net tables (t=0..50*DT) + 50 Q-net tables (t=0..49*DT)
#define NH     64      // hidden width
#define NI     65      // intervals = NH+1
#define TPAD   66      // padded interval stride in shared (bank spread)
#define NBLK   256
#define NTHR   1024

// Precomputed piecewise-linear tables.
// For table id, interval i, unit k: g_tab[id][i*NH+k] = (w3_k*A_k(i), w3_k*C_k(i))
// where z2_k(y) = A_k(i) + C_k(i)*y on interval i of the layer-1 breakpoints.
__device__ float2   g_tab[NTAB][NI * NH];
__device__ float    g_brk[NTAB][NH];
__device__ unsigned g_masks[4];     // sign(w3<0) bitmask: Y lo, Y hi, Q lo, Q hi
__device__ float    g_partial[NBLK];

// ---------------------------------------------------------------------------
// Table build: one block per (net, t). Exact reformulation of the MLP:
//   layer1: h1_j = relu(a_j + c_j*y), a_j = t*w1[0,j]+b1_j, c_j = w1[1,j]
//   layer2 pre-act on interval i: z2_k = A_k(i) + C_k(i)*y  (incremental sweep)
// ---------------------------------------------------------------------------
__global__ void build_tables(
    const float* __restrict__ Yw1, const float* __restrict__ Yb1,
    const float* __restrict__ Yw2, const float* __restrict__ Yb2,
    const float* __restrict__ Yw3,
    const float* __restrict__ Qw1, const float* __restrict__ Qb1,
    const float* __restrict__ Qw2, const float* __restrict__ Qb2,
    const float* __restrict__ Qw3)
{
    int id = blockIdx.x;
    bool isY = id < 51;
    int nstep = isY ? id : (id - 51);
    const float* w1 = isY ? Yw1 : Qw1;
    const float* b1 = isY ? Yb1 : Qb1;
    const float* w2 = isY ? Yw2 : Qw2;
    const float* b2 = isY ? Yb2 : Qb2;
    const float* w3 = isY ? Yw3 : Qw3;
    int j = threadIdx.x;   // 64 threads

    // replicate reference fp32 time accumulation (t1 = t + DT repeatedly)
    float t = 0.f;
    for (int m = 0; m < nstep; m++) t += DT;

    __shared__ float sa[NH], sc[NH], srtmp[NH];
    __shared__ float sbrkS[NH], ssgnS[NH];
    __shared__ int   sjidx[NH];
    __shared__ unsigned char sact[NH];

    float a = fmaf(t, w1[j], b1[j]);
    float c = w1[NH + j];
    float r; int sg; bool act0;
    if (c > 0.f)      { r = -a / c; sg =  1; act0 = false; }          // turns ON crossing up
    else if (c < 0.f) { r = -a / c; sg = -1; act0 = true;  }          // turns OFF crossing up
    else              { r = FLT_MAX; sg = 0; act0 = (a > 0.f); }      // constant
    sa[j] = a; sc[j] = c; srtmp[j] = r;
    sact[j] = act0 ? 1 : 0;
    __syncthreads();

    // O(n^2) rank sort of breakpoints (tie-break by index: deterministic)
    int rank = 0;
    for (int m = 0; m < NH; m++) {
        float rm = srtmp[m];
        rank += (rm < r) || (rm == r && m < j);
    }
    sjidx[rank] = j; sbrkS[rank] = r; ssgnS[rank] = (float)sg;
    __syncthreads();

    g_brk[id][j] = sbrkS[j];

    if (nstep == 0) {   // once per net: w3 sign masks
        bool neg = (w3[j] < 0.f);
        unsigned m = __ballot_sync(0xffffffffu, neg);
        if ((j & 31) == 0) g_masks[(isY ? 0 : 2) + (j >> 5)] = m;
    }

    // phase B: thread owns output unit k
    int k = j;
    float w3k = w3[k];
    float A = b2[k], C = 0.f;
    for (int jj = 0; jj < NH; jj++) {
        if (sact[jj]) {
            float w = w2[jj * NH + k];
            A = fmaf(w, sa[jj], A);
            C = fmaf(w, sc[jj], C);
        }
    }
    for (int i = 0; i < NI; i++) {
        g_tab[id][i * NH + k] = make_float2(w3k * A, w3k * C);
        if (i < NH) {
            int jj = sjidx[i];
            float w = ssgnS[i] * w2[jj * NH + k];
            A = fmaf(w, sa[jj], A);
            C = fmaf(w, sc[jj], C);
        }
    }
}

// ---------------------------------------------------------------------------
// Main simulation kernel
// ---------------------------------------------------------------------------
__device__ __forceinline__ int isearch(const float* __restrict__ brk, float y)
{
    // count of breakpoints < y, branchless binary search, result in [0,64]
    int lo = 0;
    #pragma unroll
    for (int s = 64; s > 0; s >>= 1) {
        int c2 = lo + s;
        if (c2 <= 64) { if (brk[c2 - 1] < y) lo = c2; }
    }
    return lo;
}

__device__ __forceinline__ float evalQnet(const float2* __restrict__ tab, int i, float y,
                                          unsigned mlo, unsigned mhi)
{
    float acc = 0.f;
    #pragma unroll
    for (int k = 0; k < 32; k++) {
        float2 pq = tab[k * TPAD + i];
        float v = fmaf(pq.y, y, pq.x);                  // v = w3*z
        bool on = ((mlo >> k) & 1u) ? (v < 0.f) : (v > 0.f);   // z > 0
        if (on) acc += v;
    }
    #pragma unroll
    for (int k = 0; k < 32; k++) {
        float2 pq = tab[(k + 32) * TPAD + i];
        float v = fmaf(pq.y, y, pq.x);
        bool on = ((mhi >> k) & 1u) ? (v < 0.f) : (v > 0.f);
        if (on) acc += v;
    }
    return acc;
}

__device__ __forceinline__ void evalYnet(const float2* __restrict__ tab, int i, float y,
                                         unsigned mlo, unsigned mhi,
                                         float& Y, float& dY)
{
    float a0 = 0.f, d0 = 0.f;
    #pragma unroll
    for (int k = 0; k < 32; k++) {
        float2 pq = tab[k * TPAD + i];
        float v = fmaf(pq.y, y, pq.x);
        bool on = ((mlo >> k) & 1u) ? (v < 0.f) : (v > 0.f);
        if (on) { a0 += v; d0 += pq.y; }                 // dY/dy = sum w3*C over active
    }
    #pragma unroll
    for (int k = 0; k < 32; k++) {
        float2 pq = tab[(k + 32) * TPAD + i];
        float v = fmaf(pq.y, y, pq.x);
        bool on = ((mhi >> k) & 1u) ? (v < 0.f) : (v > 0.f);
        if (on) { a0 += v; d0 += pq.y; }
    }
    Y = a0; dY = d0;
}

__global__ void __launch_bounds__(NTHR, 1) fbsnn_main(
    const float* __restrict__ dW, const float* __restrict__ y0p,
    const float* __restrict__ Yb3, const float* __restrict__ Qb3)
{
    extern __shared__ __align__(16) char smraw[];
    float2* yT  = (float2*)smraw;        // [NH][TPAD] k-major, padded
    float2* qT  = yT + NH * TPAD;
    float*  ybk = (float*)(qT + NH * TPAD);
    float*  qbk = ybk + NH;

    int tid = threadIdx.x;
    int sample = blockIdx.x * NTHR + tid;   // 256*1024 == BATCH exactly

    unsigned mYlo = g_masks[0], mYhi = g_masks[1];
    unsigned mQlo = g_masks[2], mQhi = g_masks[3];
    float b3y = Yb3[0], b3q = Qb3[0];

    // stage Y table id 0 for initial eval
    {
        const float2* src = g_tab[0];
        for (int e = tid; e < NI * NH; e += NTHR) {
            int i = e >> 6, k = e & 63;
            yT[k * TPAD + i] = src[e];
        }
        if (tid < NH) ybk[tid] = g_brk[0][tid];
    }
    __syncthreads();

    float y = y0p[0];
    float Y0, dY0;
    {
        int i = isearch(ybk, y);
        evalYnet(yT, i, y, mYlo, mYhi, Y0, dY0);
        Y0 += b3y;
    }

    float loss = 0.f;
    for (int n = 0; n < NSTEP; n++) {
        __syncthreads();     // all readers done with previous tables
        {
            const float2* sq = g_tab[51 + n];
            const float2* sy = g_tab[n + 1];
            for (int e = tid; e < NI * NH; e += NTHR) {
                int i = e >> 6, k = e & 63;
                int d = k * TPAD + i;
                qT[d] = sq[e];
                yT[d] = sy[e];
            }
            if (tid < NH) { qbk[tid] = g_brk[51 + n][tid]; ybk[tid] = g_brk[n + 1][tid]; }
        }
        __syncthreads();

        int iq = isearch(qbk, y);
        float q = evalQnet(qT, iq, y, mQlo, mQhi) + b3q;

        float dw = dW[n * BATCH + sample];
        float y1 = fmaf(q, DT, y) + SIGMA * dw;

        int iy = isearch(ybk, y1);
        float Y1, dY1;
        evalYnet(yT, iy, y1, mYlo, mYhi, Y1, dY1);
        Y1 += b3y;

        float f  = 0.5f * q * q;
        float Yt = (Y0 - f * DT) + (SIGMA * dY0) * dw;
        float rr = Y1 - Yt;
        loss = fmaf(rr, rr, loss);

        Y0 = Y1; dY0 = dY1; y = y1;
    }
    float tm = Y0 - y * y;        // terminal: (YN - yN^2)^2
    loss = fmaf(tm, tm, loss);

    // deterministic block reduction
    #pragma unroll
    for (int o = 16; o > 0; o >>= 1) loss += __shfl_down_sync(0xffffffffu, loss, o);
    __syncthreads();
    float* sred = (float*)smraw;
    int wid = tid >> 5, lane = tid & 31;
    if (lane == 0) sred[wid] = loss;
    __syncthreads();
    if (wid == 0) {
        float v = sred[lane];
        #pragma unroll
        for (int o = 16; o > 0; o >>= 1) v += __shfl_down_sync(0xffffffffu, v, o);
        if (lane == 0) g_partial[blockIdx.x] = v;
    }
}

__global__ void fbsnn_finalize(float* __restrict__ out)
{
    __shared__ float s[NBLK];
    int t = threadIdx.x;
    s[t] = g_partial[t];
    __syncthreads();
    for (int off = NBLK / 2; off > 0; off >>= 1) {
        if (t < off) s[t] += s[t + off];
        __syncthreads();
    }
    if (t == 0) out[0] = s[0] * (1.0f / (float)BATCH);
}

// ---------------------------------------------------------------------------
extern "C" void kernel_launch(void* const* d_in, const int* in_sizes, int n_in,
                              void* d_out, int out_size)
{
    const float* dW  = (const float*)d_in[0];
    const float* y0  = (const float*)d_in[1];
    const float* Yw1 = (const float*)d_in[2];
    const float* Yb1 = (const float*)d_in[3];
    const float* Yw2 = (const float*)d_in[4];
    const float* Yb2 = (const float*)d_in[5];
    const float* Yw3 = (const float*)d_in[6];
    const float* Yb3 = (const float*)d_in[7];
    const float* Qw1 = (const float*)d_in[8];
    const float* Qb1 = (const float*)d_in[9];
    const float* Qw2 = (const float*)d_in[10];
    const float* Qb2 = (const float*)d_in[11];
    const float* Qw3 = (const float*)d_in[12];
    const float* Qb3 = (const float*)d_in[13];

    build_tables<<<NTAB, NH>>>(Yw1, Yb1, Yw2, Yb2, Yw3, Qw1, Qb1, Qw2, Qb2, Qw3);

    const int smem_bytes = 2 * NH * TPAD * (int)sizeof(float2) + 2 * NH * (int)sizeof(float);
    cudaFuncSetAttribute(fbsnn_main, cudaFuncAttributeMaxDynamicSharedMemorySize, smem_bytes);
    fbsnn_main<<<NBLK, NTHR, smem_bytes>>>(dW, y0, Yb3, Qb3);

    fbsnn_finalize<<<1, NBLK>>>((float*)d_out);
}

// round 9
// speedup vs baseline: 3.9631x; 3.9631x over previous
#include <cuda_runtime.h>
#include <cfloat>
#include <cstdint>

#define DT     0.01f
#define SIGMA  0.5f
#define NSTEP  50
#define BATCH  262144
#define NTAB   101     // 51 Y-net tables (t=0..50*DT) + 50 Q-net tables (t=0..49*DT)
#define NH     64      // hidden width
#define NI     65      // intervals = NH+1
#define NBLK   256
#define NTHR   1024
#define MAXSEG 4360    // >= 64 + 65*64 breakpoints worst case
#define SORTN  8192    // bitonic sort size (pow2 >= MAXSEG)

// Pass-1 tables: per (net,t), per layer-1 interval i, per unit k:
//   g_tab[id][i*NH+k] = (w3_k*A_k(i), w3_k*C_k(i)),  z2_k(y) = A + C*y on interval i
__device__ float2   g_tab[NTAB][NI * NH];
__device__ float    g_brk[NTAB][NH];          // sorted layer-1 breakpoints (FLT_MAX sentinels)
__device__ unsigned g_masks[4];               // sign(w3<0) bitmask: Y lo, Y hi, Q lo, Q hi
__device__ float    g_partial[NBLK];

// Pass-2 collapsed tables: F(y) = alpha_s + beta_s*y on segment s; dF/dy = beta_s
__device__ float    g_sbrk[NTAB][MAXSEG];     // sorted global breakpoints (m of them)
__device__ float2   g_sseg[NTAB][MAXSEG + 1]; // (alpha, beta) per segment
__device__ int      g_m[NTAB];                // breakpoint count

// ---------------------------------------------------------------------------
// Pass 1: per-interval (A,C) tables. One block per (net, t), 64 threads.
// ---------------------------------------------------------------------------
__global__ void build_tables(
    const float* __restrict__ Yw1, const float* __restrict__ Yb1,
    const float* __restrict__ Yw2, const float* __restrict__ Yb2,
    const float* __restrict__ Yw3,
    const float* __restrict__ Qw1, const float* __restrict__ Qb1,
    const float* __restrict__ Qw2, const float* __restrict__ Qb2,
    const float* __restrict__ Qw3)
{
    int id = blockIdx.x;
    bool isY = id < 51;
    int nstep = isY ? id : (id - 51);
    const float* w1 = isY ? Yw1 : Qw1;
    const float* b1 = isY ? Yb1 : Qb1;
    const float* w2 = isY ? Yw2 : Qw2;
    const float* b2 = isY ? Yb2 : Qb2;
    const float* w3 = isY ? Yw3 : Qw3;
    int j = threadIdx.x;   // 64 threads

    // replicate reference fp32 time accumulation (t1 = t + DT repeatedly)
    float t = 0.f;
    for (int m = 0; m < nstep; m++) t += DT;

    __shared__ float sa[NH], sc[NH], srtmp[NH];
    __shared__ float sbrkS[NH], ssgnS[NH];
    __shared__ int   sjidx[NH];
    __shared__ unsigned char sact[NH];

    float a = fmaf(t, w1[j], b1[j]);
    float c = w1[NH + j];
    float r; int sg; bool act0;
    if (c > 0.f)      { r = -a / c; sg =  1; act0 = false; }
    else if (c < 0.f) { r = -a / c; sg = -1; act0 = true;  }
    else              { r = FLT_MAX; sg = 0; act0 = (a > 0.f); }
    sa[j] = a; sc[j] = c; srtmp[j] = r;
    sact[j] = act0 ? 1 : 0;
    __syncthreads();

    // O(n^2) rank sort of breakpoints (tie-break by index: deterministic)
    int rank = 0;
    for (int m = 0; m < NH; m++) {
        float rm = srtmp[m];
        rank += (rm < r) || (rm == r && m < j);
    }
    sjidx[rank] = j; sbrkS[rank] = r; ssgnS[rank] = (float)sg;
    __syncthreads();

    g_brk[id][j] = sbrkS[j];

    if (nstep == 0) {   // once per net: w3 sign masks
        bool neg = (w3[j] < 0.f);
        unsigned m = __ballot_sync(0xffffffffu, neg);
        if ((j & 31) == 0) g_masks[(isY ? 0 : 2) + (j >> 5)] = m;
    }

    // phase B: thread owns output unit k; incremental sweep over intervals
    int k = j;
    float w3k = w3[k];
    float A = b2[k], C = 0.f;
    for (int jj = 0; jj < NH; jj++) {
        if (sact[jj]) {
            float w = w2[jj * NH + k];
            A = fmaf(w, sa[jj], A);
            C = fmaf(w, sc[jj], C);
        }
    }
    for (int i = 0; i < NI; i++) {
        g_tab[id][i * NH + k] = make_float2(w3k * A, w3k * C);
        if (i < NH) {
            int jj = sjidx[i];
            float w = ssgnS[i] * w2[jj * NH + k];
            A = fmaf(w, sa[jj], A);
            C = fmaf(w, sc[jj], C);
        }
    }
}

// ---------------------------------------------------------------------------
// Pass 2: collapse each table to a single sorted piecewise-linear function.
// One block per table, 1024 threads.
// ---------------------------------------------------------------------------
__global__ void __launch_bounds__(NTHR) build_collapse()
{
    __shared__ float l1[NH];
    __shared__ float cand[SORTN];
    __shared__ int   cnt;
    int id  = blockIdx.x;
    int tid = threadIdx.x;
    bool isY = id < 51;
    unsigned mlo = g_masks[isY ? 0 : 2];
    unsigned mhi = g_masks[isY ? 1 : 3];

    if (tid == 0) cnt = 0;
    if (tid < NH) l1[tid] = g_brk[id][tid];
    __syncthreads();

    // candidates: finite layer-1 breakpoints
    if (tid < NH) {
        float r = l1[tid];
        if (r < 1e37f) { int p = atomicAdd(&cnt, 1); cand[p] = r; }
    }
    // candidates: z2_k zero crossings strictly inside each layer-1 interval
    for (int e = tid; e < NI * NH; e += NTHR) {
        int i = e >> 6;
        float2 pq = g_tab[id][e];
        if (pq.y != 0.f) {
            float ys = -pq.x / pq.y;         // = -A/C (w3 cancels; w3==0 => pq.y==0)
            float lo = (i == 0)  ? -3.0e38f : l1[i - 1];
            float hi = (i == NH) ?  3.0e38f : l1[i];
            if (ys > lo && ys < hi) { int p = atomicAdd(&cnt, 1); cand[p] = ys; }
        }
    }
    __syncthreads();
    int m = cnt;
    for (int e = m + tid; e < SORTN; e += NTHR) cand[e] = 3.4e38f;
    __syncthreads();

    // bitonic sort (deterministic final order: values sorted)
    for (int k = 2; k <= SORTN; k <<= 1) {
        for (int j = k >> 1; j > 0; j >>= 1) {
            for (int i = tid; i < SORTN; i += NTHR) {
                int ixj = i ^ j;
                if (ixj > i) {
                    float a = cand[i], b = cand[ixj];
                    bool up = ((i & k) == 0);
                    if ((a > b) == up) { cand[i] = b; cand[ixj] = a; }
                }
            }
            __syncthreads();
        }
    }

    for (int e = tid; e < m; e += NTHR) g_sbrk[id][e] = cand[e];
    if (tid == 0) g_m[id] = m;

    // per-segment (alpha, beta) via midpoint active-set classification
    for (int s = tid; s <= m; s += NTHR) {
        float ym;
        if (m == 0)       ym = 0.f;
        else if (s == 0)  ym = cand[0] - 1.0f;
        else if (s == m)  ym = cand[m - 1] + 1.0f;
        else              ym = 0.5f * (cand[s - 1] + cand[s]);

        int i1 = 0;
        #pragma unroll
        for (int j = 0; j < NH; j++) i1 += (l1[j] < ym);

        const float2* row = &g_tab[id][i1 * NH];
        float al = 0.f, be = 0.f;
        #pragma unroll 8
        for (int k2 = 0; k2 < NH; k2++) {
            float2 pq = row[k2];
            float v = fmaf(pq.y, ym, pq.x);               // v = w3*z2
            unsigned mm = (k2 < 32) ? mlo : mhi;
            bool neg = (mm >> (k2 & 31)) & 1u;
            bool on = neg ? (v < 0.f) : (v > 0.f);        // z2 > 0
            if (on) { al += pq.x; be += pq.y; }
        }
        g_sseg[id][s] = make_float2(al, be);
    }
}

// ---------------------------------------------------------------------------
// Main simulation kernel
// ---------------------------------------------------------------------------
__device__ __forceinline__ int searchm(const float* __restrict__ brk, int m, float y)
{
    // count of breakpoints < y, branchless, result in [0, m]
    int i = 0;
    #pragma unroll
    for (int s = 4096; s > 0; s >>= 1) {
        int c = i + s;
        if (c <= m && brk[c - 1] < y) i = c;
    }
    return i;
}

__global__ void __launch_bounds__(NTHR, 1) fbsnn_main(
    const float* __restrict__ dW, const float* __restrict__ y0p,
    const float* __restrict__ Yb3, const float* __restrict__ Qb3)
{
    extern __shared__ __align__(16) char smraw[];
    float2* qseg = (float2*)smraw;                 // MAXSEG+1
    float2* yseg = qseg + (MAXSEG + 1);
    float*  qbrk = (float*)(yseg + (MAXSEG + 1));  // MAXSEG
    float*  ybrk = qbrk + MAXSEG;

    int tid = threadIdx.x;
    int sample = blockIdx.x * NTHR + tid;          // 256*1024 == BATCH

    float b3y = Yb3[0], b3q = Qb3[0];

    // stage Y table 0 for initial eval
    int my0 = g_m[0];
    for (int e = tid; e <= my0; e += NTHR) {
        if (e < my0) ybrk[e] = g_sbrk[0][e];
        yseg[e] = g_sseg[0][e];
    }
    __syncthreads();

    float y = y0p[0];
    float Y0, dY0;
    {
        int i = searchm(ybrk, my0, y);
        float2 sg = yseg[i];
        Y0  = fmaf(sg.y, y, sg.x) + b3y;
        dY0 = sg.y;
    }

    float loss = 0.f;
    for (int n = 0; n < NSTEP; n++) {
        int mq = g_m[51 + n];
        int my = g_m[n + 1];
        __syncthreads();     // all readers done with previous tables
        {
            const float*  bq = g_sbrk[51 + n];
            const float2* sq = g_sseg[51 + n];
            for (int e = tid; e <= mq; e += NTHR) {
                if (e < mq) qbrk[e] = bq[e];
                qseg[e] = sq[e];
            }
            const float*  by = g_sbrk[n + 1];
            const float2* sy = g_sseg[n + 1];
            for (int e = tid; e <= my; e += NTHR) {
                if (e < my) ybrk[e] = by[e];
                yseg[e] = sy[e];
            }
        }
        __syncthreads();

        int iq = searchm(qbrk, mq, y);
        float2 qs = qseg[iq];
        float q = fmaf(qs.y, y, qs.x) + b3q;

        float dw = dW[n * BATCH + sample];
        float y1 = fmaf(q, DT, y) + SIGMA * dw;

        int iy = searchm(ybrk, my, y1);
        float2 ys = yseg[iy];
        float Y1  = fmaf(ys.y, y1, ys.x) + b3y;
        float dY1 = ys.y;

        float f  = 0.5f * q * q;
        float Yt = (Y0 - f * DT) + (SIGMA * dY0) * dw;
        float rr = Y1 - Yt;
        loss = fmaf(rr, rr, loss);

        Y0 = Y1; dY0 = dY1; y = y1;
    }
    float tm = Y0 - y * y;        // terminal: (YN - yN^2)^2
    loss = fmaf(tm, tm, loss);

    // deterministic block reduction
    #pragma unroll
    for (int o = 16; o > 0; o >>= 1) loss += __shfl_down_sync(0xffffffffu, loss, o);
    __syncthreads();
    float* sred = (float*)smraw;
    int wid = tid >> 5, lane = tid & 31;
    if (lane == 0) sred[wid] = loss;
    __syncthreads();
    if (wid == 0) {
        float v = sred[lane];
        #pragma unroll
        for (int o = 16; o > 0; o >>= 1) v += __shfl_down_sync(0xffffffffu, v, o);
        if (lane == 0) g_partial[blockIdx.x] = v;
    }
}

__global__ void fbsnn_finalize(float* __restrict__ out)
{
    __shared__ float s[NBLK];
    int t = threadIdx.x;
    s[t] = g_partial[t];
    __syncthreads();
    for (int off = NBLK / 2; off > 0; off >>= 1) {
        if (t < off) s[t] += s[t + off];
        __syncthreads();
    }
    if (t == 0) out[0] = s[0] * (1.0f / (float)BATCH);
}

// ---------------------------------------------------------------------------
extern "C" void kernel_launch(void* const* d_in, const int* in_sizes, int n_in,
                              void* d_out, int out_size)
{
    const float* dW  = (const float*)d_in[0];
    const float* y0  = (const float*)d_in[1];
    const float* Yw1 = (const float*)d_in[2];
    const float* Yb1 = (const float*)d_in[3];
    const float* Yw2 = (const float*)d_in[4];
    const float* Yb2 = (const float*)d_in[5];
    const float* Yw3 = (const float*)d_in[6];
    const float* Yb3 = (const float*)d_in[7];
    const float* Qw1 = (const float*)d_in[8];
    const float* Qb1 = (const float*)d_in[9];
    const float* Qw2 = (const float*)d_in[10];
    const float* Qb2 = (const float*)d_in[11];
    const float* Qw3 = (const float*)d_in[12];
    const float* Qb3 = (const float*)d_in[13];

    build_tables<<<NTAB, NH>>>(Yw1, Yb1, Yw2, Yb2, Yw3, Qw1, Qb1, Qw2, Qb2, Qw3);
    build_collapse<<<NTAB, NTHR>>>();

    const int smem_bytes = 2 * (MAXSEG + 1) * (int)sizeof(float2)
                         + 2 * MAXSEG * (int)sizeof(float);
    cudaFuncSetAttribute(fbsnn_main, cudaFuncAttributeMaxDynamicSharedMemorySize, smem_bytes);
    fbsnn_main<<<NBLK, NTHR, smem_bytes>>>(dW, y0, Yb3, Qb3);

    fbsnn_finalize<<<1, NBLK>>>((float*)d_out);
}

// round 13
// speedup vs baseline: 4.7048x; 1.1871x over previous
#include <cuda_runtime.h>
#include <cfloat>
#include <cstdint>

#define DT     0.01f
#define SIGMA  0.5f
#define NSTEP  50
#define BATCH  262144
#define NTAB   101     // 51 Y-net tables (t=0..50*DT) + 50 Q-net tables (t=0..49*DT)
#define NH     64      // hidden width
#define NI     65      // intervals = NH+1
#define NBLK   128     // blocks; each thread handles 2 samples
#define NTHR   1024
#define MAXSEG 4360    // >= 64 + 65*64 breakpoints worst case
#define SORTN  8192    // bitonic sort size (pow2 >= MAXSEG)
#define NBINS  4096    // uniform lookup bins per table

// Pass-1 tables: per (net,t), per layer-1 interval i, per unit k:
//   g_tab[id][i*NH+k] = (w3_k*A_k(i), w3_k*C_k(i)),  z2_k(y) = A + C*y on interval i
__device__ float2   g_tab[NTAB][NI * NH];
__device__ float    g_brk[NTAB][NH];
__device__ unsigned g_masks[4];
__device__ float    g_partial[NBLK];

// Pass-2 collapsed tables: F(y) = alpha_s + beta_s*y on segment s; dF/dy = beta_s
__device__ float    g_sbrk[NTAB][MAXSEG];       // sorted global breakpoints (m of them)
__device__ float2   g_sseg[NTAB][MAXSEG + 1];   // (alpha, beta) per segment
__device__ int      g_m[NTAB];
__device__ uint16_t g_sbin[NTAB][NBINS];        // count of brk < bin left edge
__device__ float    g_rlo[NTAB], g_scale[NTAB];

// ---------------------------------------------------------------------------
// Pass 1: per-interval (A,C) tables. One block per (net, t), 64 threads.
// ---------------------------------------------------------------------------
__global__ void build_tables(
    const float* __restrict__ Yw1, const float* __restrict__ Yb1,
    const float* __restrict__ Yw2, const float* __restrict__ Yb2,
    const float* __restrict__ Yw3,
    const float* __restrict__ Qw1, const float* __restrict__ Qb1,
    const float* __restrict__ Qw2, const float* __restrict__ Qb2,
    const float* __restrict__ Qw3)
{
    int id = blockIdx.x;
    bool isY = id < 51;
    int nstep = isY ? id : (id - 51);
    const float* w1 = isY ? Yw1 : Qw1;
    const float* b1 = isY ? Yb1 : Qb1;
    const float* w2 = isY ? Yw2 : Qw2;
    const float* b2 = isY ? Yb2 : Qb2;
    const float* w3 = isY ? Yw3 : Qw3;
    int j = threadIdx.x;

    float t = 0.f;
    for (int m = 0; m < nstep; m++) t += DT;   // replicate reference fp32 t accumulation

    __shared__ float sa[NH], sc[NH], srtmp[NH];
    __shared__ float sbrkS[NH], ssgnS[NH];
    __shared__ int   sjidx[NH];
    __shared__ unsigned char sact[NH];

    float a = fmaf(t, w1[j], b1[j]);
    float c = w1[NH + j];
    float r; int sg; bool act0;
    if (c > 0.f)      { r = -a / c; sg =  1; act0 = false; }
    else if (c < 0.f) { r = -a / c; sg = -1; act0 = true;  }
    else              { r = FLT_MAX; sg = 0; act0 = (a > 0.f); }
    sa[j] = a; sc[j] = c; srtmp[j] = r;
    sact[j] = act0 ? 1 : 0;
    __syncthreads();

    int rank = 0;
    for (int m = 0; m < NH; m++) {
        float rm = srtmp[m];
        rank += (rm < r) || (rm == r && m < j);
    }
    sjidx[rank] = j; sbrkS[rank] = r; ssgnS[rank] = (float)sg;
    __syncthreads();

    g_brk[id][j] = sbrkS[j];

    if (nstep == 0) {
        bool neg = (w3[j] < 0.f);
        unsigned m = __ballot_sync(0xffffffffu, neg);
        if ((j & 31) == 0) g_masks[(isY ? 0 : 2) + (j >> 5)] = m;
    }

    int k = j;
    float w3k = w3[k];
    float A = b2[k], C = 0.f;
    for (int jj = 0; jj < NH; jj++) {
        if (sact[jj]) {
            float w = w2[jj * NH + k];
            A = fmaf(w, sa[jj], A);
            C = fmaf(w, sc[jj], C);
        }
    }
    for (int i = 0; i < NI; i++) {
        g_tab[id][i * NH + k] = make_float2(w3k * A, w3k * C);
        if (i < NH) {
            int jj = sjidx[i];
            float w = ssgnS[i] * w2[jj * NH + k];
            A = fmaf(w, sa[jj], A);
            C = fmaf(w, sc[jj], C);
        }
    }
}

// ---------------------------------------------------------------------------
// Pass 2: collapse each table to one sorted PWL function + uniform bin index.
// One block per table, 1024 threads.
// ---------------------------------------------------------------------------
__global__ void __launch_bounds__(NTHR) build_collapse()
{
    __shared__ float l1[NH];
    __shared__ float cand[SORTN];
    __shared__ int   cnt;
    int id  = blockIdx.x;
    int tid = threadIdx.x;
    bool isY = id < 51;
    unsigned mlo = g_masks[isY ? 0 : 2];
    unsigned mhi = g_masks[isY ? 1 : 3];

    if (tid == 0) cnt = 0;
    if (tid < NH) l1[tid] = g_brk[id][tid];
    __syncthreads();

    if (tid < NH) {
        float r = l1[tid];
        if (r < 1e37f) { int p = atomicAdd(&cnt, 1); cand[p] = r; }
    }
    for (int e = tid; e < NI * NH; e += NTHR) {
        int i = e >> 6;
        float2 pq = g_tab[id][e];
        if (pq.y != 0.f) {
            float ys = -pq.x / pq.y;
            float lo = (i == 0)  ? -3.0e38f : l1[i - 1];
            float hi = (i == NH) ?  3.0e38f : l1[i];
            if (ys > lo && ys < hi) { int p = atomicAdd(&cnt, 1); cand[p] = ys; }
        }
    }
    __syncthreads();
    int m = cnt;
    for (int e = m + tid; e < SORTN; e += NTHR) cand[e] = 3.4e38f;
    __syncthreads();

    // bitonic sort
    for (int k = 2; k <= SORTN; k <<= 1) {
        for (int j = k >> 1; j > 0; j >>= 1) {
            for (int i = tid; i < SORTN; i += NTHR) {
                int ixj = i ^ j;
                if (ixj > i) {
                    float a = cand[i], b = cand[ixj];
                    bool up = ((i & k) == 0);
                    if ((a > b) == up) { cand[i] = b; cand[ixj] = a; }
                }
            }
            __syncthreads();
        }
    }

    for (int e = tid; e < m; e += NTHR) g_sbrk[id][e] = cand[e];
    if (tid == 0) g_m[id] = m;

    // uniform bin index over [rlo, rhi]
    float rlo = (m > 0) ? cand[0] : 0.f;
    float rhi = (m > 0) ? cand[m - 1] : 0.f;
    float width = rhi - rlo;
    float scale = (m >= 2 && width > 0.f) ? ((float)NBINS / width) : 0.f;
    if (tid == 0) { g_rlo[id] = rlo; g_scale[id] = scale; }

    for (int b = tid; b < NBINS; b += NTHR) {
        uint16_t cntb = 0;
        if (m > 0 && scale > 0.f) {
            float edge = rlo + ((float)b) * width * (1.f / (float)NBINS);
            int lo = 0;
            #pragma unroll
            for (int s = SORTN; s > 0; s >>= 1) {
                int c = lo + s;
                if (c <= SORTN && cand[c - 1] < edge) lo = c;
            }
            cntb = (uint16_t)lo;
        }
        g_sbin[id][b] = cntb;
    }

    // per-segment (alpha, beta) via midpoint active-set classification
    for (int s = tid; s <= m; s += NTHR) {
        float ym;
        if (m == 0)       ym = 0.f;
        else if (s == 0)  ym = cand[0] - 1.0f;
        else if (s == m)  ym = cand[m - 1] + 1.0f;
        else              ym = 0.5f * (cand[s - 1] + cand[s]);

        int i1 = 0;
        #pragma unroll
        for (int j = 0; j < NH; j++) i1 += (l1[j] < ym);

        const float2* row = &g_tab[id][i1 * NH];
        float al = 0.f, be = 0.f;
        #pragma unroll 8
        for (int k2 = 0; k2 < NH; k2++) {
            float2 pq = row[k2];
            float v = fmaf(pq.y, ym, pq.x);
            unsigned mm = (k2 < 32) ? mlo : mhi;
            bool neg = (mm >> (k2 & 31)) & 1u;
            bool on = neg ? (v < 0.f) : (v > 0.f);
            if (on) { al += pq.x; be += pq.y; }
        }
        g_sseg[id][s] = make_float2(al, be);
    }
}

// ---------------------------------------------------------------------------
// Main simulation kernel: 2 samples per thread, bin-accelerated lookup.
// ---------------------------------------------------------------------------
__device__ __forceinline__ int lookup(const float* __restrict__ brk,
                                      const uint16_t* __restrict__ bin,
                                      int m, float rlo, float scale, float y)
{
    float bf = (y - rlo) * scale;
    int b = (bf > 0.f) ? ((bf < (float)(NBINS - 1)) ? (int)bf : (NBINS - 1)) : 0;
    int i = bin[b];
    // exact lower_bound fix-up (each loop usually 0-1 iterations)
    while (i < m && brk[i] < y) ++i;
    while (i > 0 && brk[i - 1] >= y) --i;
    return i;
}

__global__ void __launch_bounds__(NTHR, 1) fbsnn_main(
    const float* __restrict__ dW, const float* __restrict__ y0p,
    const float* __restrict__ Yb3, const float* __restrict__ Qb3)
{
    extern __shared__ __align__(16) char smraw[];
    float2*   qseg = (float2*)smraw;                   // MAXSEG+1
    float2*   yseg = qseg + (MAXSEG + 1);
    float*    qbrk = (float*)(yseg + (MAXSEG + 1));    // MAXSEG
    float*    ybrk = qbrk + MAXSEG;
    uint16_t* qbin = (uint16_t*)(ybrk + MAXSEG);       // NBINS
    uint16_t* ybin = qbin + NBINS;

    int tid = threadIdx.x;
    int sA = blockIdx.x * NTHR + tid;     // 128*1024 == 131072
    int sB = sA + (NBLK * NTHR);          // second half of batch

    float b3y = Yb3[0], b3q = Qb3[0];

    // stage Y table 0 for initial eval
    int   my0 = g_m[0];
    float yrlo = g_rlo[0], ysc = g_scale[0];
    for (int e = tid; e <= my0; e += NTHR) {
        if (e < my0) ybrk[e] = g_sbrk[0][e];
        yseg[e] = g_sseg[0][e];
    }
    {
        const uint32_t* src = (const uint32_t*)g_sbin[0];
        uint32_t* dst = (uint32_t*)ybin;
        for (int e = tid; e < NBINS / 2; e += NTHR) dst[e] = src[e];
    }
    __syncthreads();

    float yA = y0p[0], yB = yA;
    float Y0A, dY0A, Y0B, dY0B;
    {
        int iA = lookup(ybrk, ybin, my0, yrlo, ysc, yA);
        float2 sgA = yseg[iA];
        Y0A = fmaf(sgA.y, yA, sgA.x) + b3y;  dY0A = sgA.y;
        Y0B = Y0A;  dY0B = dY0A;             // same y0 for all samples
    }

    float lossA = 0.f, lossB = 0.f;
    for (int n = 0; n < NSTEP; n++) {
        int mq = g_m[51 + n];
        int my = g_m[n + 1];
        float qrlo = g_rlo[51 + n], qsc = g_scale[51 + n];
        yrlo = g_rlo[n + 1]; ysc = g_scale[n + 1];

        float dwA = dW[n * BATCH + sA];
        float dwB = dW[n * BATCH + sB];

        __syncthreads();     // all readers done with previous tables
        {
            const float*  bq = g_sbrk[51 + n];
            const float2* sq = g_sseg[51 + n];
            for (int e = tid; e <= mq; e += NTHR) {
                if (e < mq) qbrk[e] = bq[e];
                qseg[e] = sq[e];
            }
            const float*  by = g_sbrk[n + 1];
            const float2* sy = g_sseg[n + 1];
            for (int e = tid; e <= my; e += NTHR) {
                if (e < my) ybrk[e] = by[e];
                yseg[e] = sy[e];
            }
            const uint32_t* sbq = (const uint32_t*)g_sbin[51 + n];
            const uint32_t* sby = (const uint32_t*)g_sbin[n + 1];
            uint32_t* dbq = (uint32_t*)qbin;
            uint32_t* dby = (uint32_t*)ybin;
            for (int e = tid; e < NBINS / 2; e += NTHR) { dbq[e] = sbq[e]; dby[e] = sby[e]; }
        }
        __syncthreads();

        // two independent samples -> interleaved dependent chains
        int iqA = lookup(qbrk, qbin, mq, qrlo, qsc, yA);
        int iqB = lookup(qbrk, qbin, mq, qrlo, qsc, yB);
        float2 qsA = qseg[iqA];
        float2 qsB = qseg[iqB];
        float qA = fmaf(qsA.y, yA, qsA.x) + b3q;
        float qB = fmaf(qsB.y, yB, qsB.x) + b3q;

        float y1A = fmaf(qA, DT, yA) + SIGMA * dwA;
        float y1B = fmaf(qB, DT, yB) + SIGMA * dwB;

        int iyA = lookup(ybrk, ybin, my, yrlo, ysc, y1A);
        int iyB = lookup(ybrk, ybin, my, yrlo, ysc, y1B);
        float2 ysA = yseg[iyA];
        float2 ysB = yseg[iyB];
        float Y1A = fmaf(ysA.y, y1A, ysA.x) + b3y;
        float Y1B = fmaf(ysB.y, y1B, ysB.x) + b3y;

        float fA  = 0.5f * qA * qA;
        float fB  = 0.5f * qB * qB;
        float YtA = (Y0A - fA * DT) + (SIGMA * dY0A) * dwA;
        float YtB = (Y0B - fB * DT) + (SIGMA * dY0B) * dwB;
        float rA = Y1A - YtA;
        float rB = Y1B - YtB;
        lossA = fmaf(rA, rA, lossA);
        lossB = fmaf(rB, rB, lossB);

        Y0A = Y1A; dY0A = ysA.y; yA = y1A;
        Y0B = Y1B; dY0B = ysB.y; yB = y1B;
    }
    float tmA = Y0A - yA * yA;
    float tmB = Y0B - yB * yB;
    float loss = fmaf(tmA, tmA, lossA) + fmaf(tmB, tmB, lossB);

    // deterministic block reduction
    #pragma unroll
    for (int o = 16; o > 0; o >>= 1) loss += __shfl_down_sync(0xffffffffu, loss, o);
    __syncthreads();
    float* sred = (float*)smraw;
    int wid = tid >> 5, lane = tid & 31;
    if (lane == 0) sred[wid] = loss;
    __syncthreads();
    if (wid == 0) {
        float v = sred[lane];
        #pragma unroll
        for (int o = 16; o > 0; o >>= 1) v += __shfl_down_sync(0xffffffffu, v, o);
        if (lane == 0) g_partial[blockIdx.x] = v;
    }
}

__global__ void fbsnn_finalize(float* __restrict__ out)
{
    __shared__ float s[NBLK];
    int t = threadIdx.x;
    s[t] = g_partial[t];
    __syncthreads();
    for (int off = NBLK / 2; off > 0; off >>= 1) {
        if (t < off) s[t] += s[t + off];
        __syncthreads();
    }
    if (t == 0) out[0] = s[0] * (1.0f / (float)BATCH);
}

// ---------------------------------------------------------------------------
extern "C" void kernel_launch(void* const* d_in, const int* in_sizes, int n_in,
                              void* d_out, int out_size)
{
    const float* dW  = (const float*)d_in[0];
    const float* y0  = (const float*)d_in[1];
    const float* Yw1 = (const float*)d_in[2];
    const float* Yb1 = (const float*)d_in[3];
    const float* Yw2 = (const float*)d_in[4];
    const float* Yb2 = (const float*)d_in[5];
    const float* Yw3 = (const float*)d_in[6];
    const float* Yb3 = (const float*)d_in[7];
    const float* Qw1 = (const float*)d_in[8];
    const float* Qb1 = (const float*)d_in[9];
    const float* Qw2 = (const float*)d_in[10];
    const float* Qb2 = (const float*)d_in[11];
    const float* Qw3 = (const float*)d_in[12];
    const float* Qb3 = (const float*)d_in[13];

    build_tables<<<NTAB, NH>>>(Yw1, Yb1, Yw2, Yb2, Yw3, Qw1, Qb1, Qw2, Qb2, Qw3);
    build_collapse<<<NTAB, NTHR>>>();

    const int smem_bytes = 2 * (MAXSEG + 1) * (int)sizeof(float2)
                         + 2 * MAXSEG * (int)sizeof(float)
                         + 2 * NBINS * (int)sizeof(uint16_t);
    cudaFuncSetAttribute(fbsnn_main, cudaFuncAttributeMaxDynamicSharedMemorySize, smem_bytes);
    fbsnn_main<<<NBLK, NTHR, smem_bytes>>>(dW, y0, Yb3, Qb3);

    fbsnn_finalize<<<1, NBLK>>>((float*)d_out);
}

// round 16
// speedup vs baseline: 4.7443x; 1.0084x over previous
#include <cuda_runtime.h>
#include <cfloat>
#include <cstdint>

#define DT     0.01f
#define SIGMA  0.5f
#define NSTEP  50
#define BATCH  262144
#define NTAB   101     // 51 Y-net tables (t=0..50*DT) + 50 Q-net tables (t=0..49*DT)
#define NH     64      // hidden width
#define NI     65      // intervals = NH+1
#define NTHRB  1024    // build_collapse threads
#define MAXSEG 4360    // >= 64 + 65*64 breakpoints worst case
#define SORTN  8192    // bitonic sort size (pow2 >= MAXSEG)
#define NBINS  8192    // uniform lookup bins per table

#define MBLK   256     // main kernel blocks
#define MTHR   512     // main kernel threads/block (each thread: 2 samples)

// Pass-1 tables: per (net,t), per layer-1 interval i, per unit k:
//   g_tab[id][i*NH+k] = (w3_k*A_k(i), w3_k*C_k(i)),  z2_k(y) = A + C*y on interval i
__device__ float2   g_tab[NTAB][NI * NH];
__device__ float    g_brk[NTAB][NH];
__device__ unsigned g_masks[4];
__device__ float    g_partial[MBLK];

// Pass-2 collapsed tables: F(y) = alpha_s + beta_s*y on segment s; dF/dy = beta_s
__device__ float    g_sbrk[NTAB][MAXSEG];       // sorted global breakpoints (m of them)
__device__ float2   g_sseg[NTAB][MAXSEG + 1];   // (alpha, beta) per segment
__device__ int      g_m[NTAB];
__device__ uint16_t g_sbin[NTAB][NBINS + 2];    // prefix counts at bin edges b=0..NBINS
__device__ float    g_rlo[NTAB], g_scale[NTAB];

// ---------------------------------------------------------------------------
// Pass 1: per-interval (A,C) tables. One block per (net, t), 64 threads.
// ---------------------------------------------------------------------------
__global__ void build_tables(
    const float* __restrict__ Yw1, const float* __restrict__ Yb1,
    const float* __restrict__ Yw2, const float* __restrict__ Yb2,
    const float* __restrict__ Yw3,
    const float* __restrict__ Qw1, const float* __restrict__ Qb1,
    const float* __restrict__ Qw2, const float* __restrict__ Qb2,
    const float* __restrict__ Qw3)
{
    int id = blockIdx.x;
    bool isY = id < 51;
    int nstep = isY ? id : (id - 51);
    const float* w1 = isY ? Yw1 : Qw1;
    const float* b1 = isY ? Yb1 : Qb1;
    const float* w2 = isY ? Yw2 : Qw2;
    const float* b2 = isY ? Yb2 : Qb2;
    const float* w3 = isY ? Yw3 : Qw3;
    int j = threadIdx.x;

    float t = 0.f;
    for (int m = 0; m < nstep; m++) t += DT;   // replicate reference fp32 t accumulation

    __shared__ float sa[NH], sc[NH], srtmp[NH];
    __shared__ float sbrkS[NH], ssgnS[NH];
    __shared__ int   sjidx[NH];
    __shared__ unsigned char sact[NH];

    float a = fmaf(t, w1[j], b1[j]);
    float c = w1[NH + j];
    float r; int sg; bool act0;
    if (c > 0.f)      { r = -a / c; sg =  1; act0 = false; }
    else if (c < 0.f) { r = -a / c; sg = -1; act0 = true;  }
    else              { r = FLT_MAX; sg = 0; act0 = (a > 0.f); }
    sa[j] = a; sc[j] = c; srtmp[j] = r;
    sact[j] = act0 ? 1 : 0;
    __syncthreads();

    int rank = 0;
    for (int m = 0; m < NH; m++) {
        float rm = srtmp[m];
        rank += (rm < r) || (rm == r && m < j);
    }
    sjidx[rank] = j; sbrkS[rank] = r; ssgnS[rank] = (float)sg;
    __syncthreads();

    g_brk[id][j] = sbrkS[j];

    if (nstep == 0) {
        bool neg = (w3[j] < 0.f);
        unsigned m = __ballot_sync(0xffffffffu, neg);
        if ((j & 31) == 0) g_masks[(isY ? 0 : 2) + (j >> 5)] = m;
    }

    int k = j;
    float w3k = w3[k];
    float A = b2[k], C = 0.f;
    for (int jj = 0; jj < NH; jj++) {
        if (sact[jj]) {
            float w = w2[jj * NH + k];
            A = fmaf(w, sa[jj], A);
            C = fmaf(w, sc[jj], C);
        }
    }
    for (int i = 0; i < NI; i++) {
        g_tab[id][i * NH + k] = make_float2(w3k * A, w3k * C);
        if (i < NH) {
            int jj = sjidx[i];
            float w = ssgnS[i] * w2[jj * NH + k];
            A = fmaf(w, sa[jj], A);
            C = fmaf(w, sc[jj], C);
        }
    }
}

// ---------------------------------------------------------------------------
// Pass 2: collapse each table to one sorted PWL function + bin prefix counts.
// One block per table, 1024 threads.
// ---------------------------------------------------------------------------
__global__ void __launch_bounds__(NTHRB) build_collapse()
{
    __shared__ float l1[NH];
    __shared__ float cand[SORTN];
    __shared__ int   cnt;
    int id  = blockIdx.x;
    int tid = threadIdx.x;
    bool isY = id < 51;
    unsigned mlo = g_masks[isY ? 0 : 2];
    unsigned mhi = g_masks[isY ? 1 : 3];

    if (tid == 0) cnt = 0;
    if (tid < NH) l1[tid] = g_brk[id][tid];
    __syncthreads();

    if (tid < NH) {
        float r = l1[tid];
        if (r < 1e37f) { int p = atomicAdd(&cnt, 1); cand[p] = r; }
    }
    for (int e = tid; e < NI * NH; e += NTHRB) {
        int i = e >> 6;
        float2 pq = g_tab[id][e];
        if (pq.y != 0.f) {
            float ys = -pq.x / pq.y;
            float lo = (i == 0)  ? -3.0e38f : l1[i - 1];
            float hi = (i == NH) ?  3.0e38f : l1[i];
            if (ys > lo && ys < hi) { int p = atomicAdd(&cnt, 1); cand[p] = ys; }
        }
    }
    __syncthreads();
    int m = cnt;
    for (int e = m + tid; e < SORTN; e += NTHRB) cand[e] = 3.4e38f;
    __syncthreads();

    // bitonic sort
    for (int k = 2; k <= SORTN; k <<= 1) {
        for (int j = k >> 1; j > 0; j >>= 1) {
            for (int i = tid; i < SORTN; i += NTHRB) {
                int ixj = i ^ j;
                if (ixj > i) {
                    float a = cand[i], b = cand[ixj];
                    bool up = ((i & k) == 0);
                    if ((a > b) == up) { cand[i] = b; cand[ixj] = a; }
                }
            }
            __syncthreads();
        }
    }

    for (int e = tid; e < m; e += NTHRB) g_sbrk[id][e] = cand[e];
    if (tid == 0) g_m[id] = m;

    // bin prefix counts at NBINS+1 edges over [rlo, rhi]
    float rlo = (m > 0) ? cand[0] : 0.f;
    float rhi = (m > 0) ? cand[m - 1] : 0.f;
    float width = rhi - rlo;
    float scale = (m >= 2 && width > 0.f) ? ((float)NBINS / width) : 0.f;
    if (tid == 0) { g_rlo[id] = rlo; g_scale[id] = scale; }

    for (int b = tid; b <= NBINS; b += NTHRB) {
        uint16_t cntb = 0;
        if (m > 0 && scale > 0.f) {
            float edge = rlo + ((float)b) * width * (1.f / (float)NBINS);
            int lo = 0;
            #pragma unroll
            for (int s = SORTN; s > 0; s >>= 1) {
                int c = lo + s;
                if (c <= SORTN && cand[c - 1] < edge) lo = c;
            }
            cntb = (uint16_t)lo;
        }
        g_sbin[id][b] = cntb;
    }

    // per-segment (alpha, beta) via midpoint active-set classification
    for (int s = tid; s <= m; s += NTHRB) {
        float ym;
        if (m == 0)       ym = 0.f;
        else if (s == 0)  ym = cand[0] - 1.0f;
        else if (s == m)  ym = cand[m - 1] + 1.0f;
        else              ym = 0.5f * (cand[s - 1] + cand[s]);

        int i1 = 0;
        #pragma unroll
        for (int j = 0; j < NH; j++) i1 += (l1[j] < ym);

        const float2* row = &g_tab[id][i1 * NH];
        float al = 0.f, be = 0.f;
        #pragma unroll 8
        for (int k2 = 0; k2 < NH; k2++) {
            float2 pq = row[k2];
            float v = fmaf(pq.y, ym, pq.x);
            unsigned mm = (k2 < 32) ? mlo : mhi;
            bool neg = (mm >> (k2 & 31)) & 1u;
            bool on = neg ? (v < 0.f) : (v > 0.f);
            if (on) { al += pq.x; be += pq.y; }
        }
        g_sseg[id][s] = make_float2(al, be);
    }
}

// ---------------------------------------------------------------------------
// Main simulation kernel: no smem tables, no per-step barriers. All table
// reads via __ldg (L1-resident working set). Bounded bin-refined search.
// ---------------------------------------------------------------------------
__device__ __forceinline__ int lookup(const float* __restrict__ brk,
                                      const uint16_t* __restrict__ bin,
                                      int m, float rlo, float scale, float y)
{
    float bf = (y - rlo) * scale;
    int b = (bf > 0.f) ? ((bf < (float)(NBINS - 1)) ? (int)bf : (NBINS - 1)) : 0;
    int i0 = __ldg(bin + b);
    int i1 = __ldg(bin + b + 1);
    // lower_bound within [i0, i1] (typical span 0-2, worst ~log2 of hot bin)
    while (i0 < i1) {
        int mid = (i0 + i1) >> 1;
        if (__ldg(brk + mid) < y) i0 = mid + 1; else i1 = mid;
    }
    // exact safety fix-up for fp edge rounding (0-1 steps)
    while (i0 < m && __ldg(brk + i0) < y) ++i0;
    while (i0 > 0 && __ldg(brk + i0 - 1) >= y) --i0;
    return i0;
}

__global__ void __launch_bounds__(MTHR) fbsnn_main(
    const float* __restrict__ dW, const float* __restrict__ y0p,
    const float* __restrict__ Yb3, const float* __restrict__ Qb3)
{
    int tid = threadIdx.x;
    int sA = blockIdx.x * MTHR + tid;      // 256*512 = 131072
    int sB = sA + (MBLK * MTHR);           // second half of batch

    float b3y = Yb3[0], b3q = Qb3[0];

    float yA = y0p[0], yB = yA;
    float Y0A, dY0A, Y0B, dY0B;
    {
        int my0 = g_m[0];
        int i = lookup(g_sbrk[0], g_sbin[0], my0, g_rlo[0], g_scale[0], yA);
        float2 sg = __ldg(&g_sseg[0][i]);
        Y0A = fmaf(sg.y, yA, sg.x) + b3y;  dY0A = sg.y;
        Y0B = Y0A;  dY0B = dY0A;           // same y0 for all samples
    }

    float lossA = 0.f, lossB = 0.f;
    for (int n = 0; n < NSTEP; n++) {
        const float*    qbrk = g_sbrk[51 + n];
        const float2*   qseg = g_sseg[51 + n];
        const uint16_t* qbin = g_sbin[51 + n];
        const float*    ybrk = g_sbrk[n + 1];
        const float2*   yseg = g_sseg[n + 1];
        const uint16_t* ybin = g_sbin[n + 1];
        int   mq   = g_m[51 + n],   my  = g_m[n + 1];
        float qrlo = g_rlo[51 + n], qsc = g_scale[51 + n];
        float yrlo = g_rlo[n + 1],  ysc = g_scale[n + 1];

        float dwA = dW[n * BATCH + sA];
        float dwB = dW[n * BATCH + sB];

        int iqA = lookup(qbrk, qbin, mq, qrlo, qsc, yA);
        int iqB = lookup(qbrk, qbin, mq, qrlo, qsc, yB);
        float2 qsA = __ldg(&qseg[iqA]);
        float2 qsB = __ldg(&qseg[iqB]);
        float qA = fmaf(qsA.y, yA, qsA.x) + b3q;
        float qB = fmaf(qsB.y, yB, qsB.x) + b3q;

        float y1A = fmaf(qA, DT, yA) + SIGMA * dwA;
        float y1B = fmaf(qB, DT, yB) + SIGMA * dwB;

        int iyA = lookup(ybrk, ybin, my, yrlo, ysc, y1A);
        int iyB = lookup(ybrk, ybin, my, yrlo, ysc, y1B);
        float2 ysA = __ldg(&yseg[iyA]);
        float2 ysB = __ldg(&yseg[iyB]);
        float Y1A = fmaf(ysA.y, y1A, ysA.x) + b3y;
        float Y1B = fmaf(ysB.y, y1B, ysB.x) + b3y;

        float fA  = 0.5f * qA * qA;
        float fB  = 0.5f * qB * qB;
        float YtA = (Y0A - fA * DT) + (SIGMA * dY0A) * dwA;
        float YtB = (Y0B - fB * DT) + (SIGMA * dY0B) * dwB;
        float rA = Y1A - YtA;
        float rB = Y1B - YtB;
        lossA = fmaf(rA, rA, lossA);
        lossB = fmaf(rB, rB, lossB);

        Y0A = Y1A; dY0A = ysA.y; yA = y1A;
        Y0B = Y1B; dY0B = ysB.y; yB = y1B;
    }
    float tmA = Y0A - yA * yA;
    float tmB = Y0B - yB * yB;
    float loss = fmaf(tmA, tmA, lossA) + fmaf(tmB, tmB, lossB);

    // deterministic block reduction
    __shared__ float sred[MTHR / 32];
    #pragma unroll
    for (int o = 16; o > 0; o >>= 1) loss += __shfl_down_sync(0xffffffffu, loss, o);
    int wid = tid >> 5, lane = tid & 31;
    if (lane == 0) sred[wid] = loss;
    __syncthreads();
    if (wid == 0) {
        float v = (lane < MTHR / 32) ? sred[lane] : 0.f;
        #pragma unroll
        for (int o = 8; o > 0; o >>= 1) v += __shfl_down_sync(0xffffffffu, v, o);
        if (lane == 0) g_partial[blockIdx.x] = v;
    }
}

__global__ void fbsnn_finalize(float* __restrict__ out)
{
    __shared__ float s[MBLK];
    int t = threadIdx.x;
    s[t] = g_partial[t];
    __syncthreads();
    for (int off = MBLK / 2; off > 0; off >>= 1) {
        if (t < off) s[t] += s[t + off];
        __syncthreads();
    }
    if (t == 0) out[0] = s[0] * (1.0f / (float)BATCH);
}

// ---------------------------------------------------------------------------
extern "C" void kernel_launch(void* const* d_in, const int* in_sizes, int n_in,
                              void* d_out, int out_size)
{
    const float* dW  = (const float*)d_in[0];
    const float* y0  = (const float*)d_in[1];
    const float* Yw1 = (const float*)d_in[2];
    const float* Yb1 = (const float*)d_in[3];
    const float* Yw2 = (const float*)d_in[4];
    const float* Yb2 = (const float*)d_in[5];
    const float* Yw3 = (const float*)d_in[6];
    const float* Yb3 = (const float*)d_in[7];
    const float* Qw1 = (const float*)d_in[8];
    const float* Qb1 = (const float*)d_in[9];
    const float* Qw2 = (const float*)d_in[10];
    const float* Qb2 = (const float*)d_in[11];
    const float* Qw3 = (const float*)d_in[12];
    const float* Qb3 = (const float*)d_in[13];

    build_tables<<<NTAB, NH>>>(Yw1, Yb1, Yw2, Yb2, Yw3, Qw1, Qb1, Qw2, Qb2, Qw3);
    build_collapse<<<NTAB, NTHRB>>>();

    fbsnn_main<<<MBLK, MTHR>>>(dW, y0, Yb3, Qb3);

    fbsnn_finalize<<<1, MBLK>>>((float*)d_out);
}